// round 7
// baseline (speedup 1.0000x reference)
#include <cuda_runtime.h>
#include <math.h>
#include <stdint.h>

#define N_NODES 114688
#define N_EDGES 917504
#define MAXC    256
#define BN_EPS  1e-5f
#define ONE_STEP 14
#define NGRAPH  (N_NODES / ONE_STEP)

// ---------------- scratch (static device globals; no allocation) ----------------
__device__ __align__(16) float  g_buf0[(size_t)N_NODES * MAXC];
__device__ __align__(16) float  g_buf1[(size_t)N_NODES * MAXC];
__device__ __align__(16) float  g_buf2[(size_t)N_NODES * MAXC];
__device__ float  g_dis[N_NODES];
__device__ double g_sum[MAXC], g_sumsq[MAXC];
__device__ __align__(16) float g_scaleA[MAXC], g_shiftA[MAXC];
__device__ __align__(16) float g_scale4[32],  g_shift4[32];
__device__ __align__(16) float g_scaleG1[16], g_shiftG1[16];
__device__ __align__(16) float g_scaleG2[4],  g_shiftG2[4];

__device__ __forceinline__ uint32_t f2tf32(float x) {
    uint32_t r;
    asm("cvt.rna.tf32.f32 %0, %1;" : "=r"(r) : "f"(x));
    return r;
}
// split-precision: v = hi + lo with both representable in tf32
__device__ __forceinline__ void split_tf32(float v, uint32_t& hi, uint32_t& lo) {
    hi = f2tf32(v);
    lo = f2tf32(v - __uint_as_float(hi));
}
__device__ __forceinline__ void mma_tf32(float* c, const uint32_t* a, uint32_t b0, uint32_t b1) {
    asm volatile(
        "mma.sync.aligned.m16n8k8.row.col.f32.tf32.tf32.f32 "
        "{%0,%1,%2,%3}, {%4,%5,%6,%7}, {%8,%9}, {%0,%1,%2,%3};"
        : "+f"(c[0]), "+f"(c[1]), "+f"(c[2]), "+f"(c[3])
        : "r"(a[0]), "r"(a[1]), "r"(a[2]), "r"(a[3]), "r"(b0), "r"(b1));
}

// ---------------- degree / normalization ----------------
__global__ void deg_zero_kernel() {
    int i = blockIdx.x * blockDim.x + threadIdx.x;
    if (i < N_NODES) g_dis[i] = 0.f;
}
__global__ void deg_count_kernel(const int* __restrict__ ei) {
    int e = blockIdx.x * blockDim.x + threadIdx.x;
    if (e < N_EDGES) atomicAdd(&g_dis[ei[N_EDGES + e]], 1.0f);
}
__global__ void deg_rsqrt_kernel() {
    int i = blockIdx.x * blockDim.x + threadIdx.x;
    if (i < N_NODES) g_dis[i] = rsqrtf(g_dis[i] + 1.0f);
}

// ---------------- 3xTF32 mma.sync GEMM (fp32-accurate) ----------------
// C[N,CO] = A'[N,K] @ W[K,CO]; A' = A (or BN affine). Block tile 128 x BN.
// 8 warps (4M x 2N), warp tile 32 x BN/2, BK=32, double-buffered fp32 smem.
// Each operand split hi/lo in registers; 3 MMAs (hh, lh, hl) per fragment.
// EPI 0: out=z, self_out=dis^2*z.  EPI 1: out=relu(z+bias).
template<int CO, int BN, int K, bool AFFINE, int EPI>
__global__ __launch_bounds__(256)
void mma_gemm_kernel(const float* __restrict__ A, const float* __restrict__ W,
                     const float* __restrict__ bias, float* __restrict__ out,
                     float* __restrict__ self_out) {
    const int ASTR = 36;            // 128x32 A tile, padded rows
    const int BSTR = BN + 8;        // 32xBN B tile, padded rows
    const int AW = 128 * ASTR;
    const int BW = 32 * BSTR;
    extern __shared__ float sm[];
    float* const Ab[2] = { sm, sm + AW };
    float* const Bb[2] = { sm + 2 * AW, sm + 2 * AW + BW };
    float* const scs = sm + 2 * AW + 2 * BW;
    float* const sfs = scs + K;

    const int tid = threadIdx.x;
    const int lane = tid & 31, wid = tid >> 5;
    const int warpM = wid & 3, warpN = wid >> 2;
    const int WN = BN / 2;
    const int NT = WN / 8;
    const int g = lane >> 2, kk = lane & 3;
    const int row0 = blockIdx.y * 128;
    const int col0 = blockIdx.x * BN;

    if (AFFINE) {
        for (int i = tid; i < K; i += 256) { scs[i] = g_scaleA[i]; sfs[i] = g_shiftA[i]; }
        __syncthreads();
    }

    float acc[2][NT][4];
#pragma unroll
    for (int t = 0; t < 2; t++)
#pragma unroll
        for (int j = 0; j < NT; j++)
#pragma unroll
            for (int q = 0; q < 4; q++) acc[t][j][q] = 0.f;

    const int NCH = K / 32;
    for (int ch = 0; ch < NCH; ch++) {
        float* As = Ab[ch & 1];
        float* Bs = Bb[ch & 1];
        const int k0 = ch * 32;
        // A tile: 128 rows x 32 k (fp32)
#pragma unroll
        for (int i = 0; i < 4; i++) {
            int f = tid + i * 256;
            int r = f >> 3;
            int kq = (f & 7) * 4;
            float4 v = *(const float4*)(A + (size_t)(row0 + r) * K + k0 + kq);
            if (AFFINE) {
                v.x = fmaf(v.x, scs[k0 + kq + 0], sfs[k0 + kq + 0]);
                v.y = fmaf(v.y, scs[k0 + kq + 1], sfs[k0 + kq + 1]);
                v.z = fmaf(v.z, scs[k0 + kq + 2], sfs[k0 + kq + 2]);
                v.w = fmaf(v.w, scs[k0 + kq + 3], sfs[k0 + kq + 3]);
            }
            *(float4*)&As[r * ASTR + kq] = v;
        }
        // B tile: 32 rows x BN cols (fp32)
        const int NBF = 32 * BN / 4 / 256;
#pragma unroll
        for (int i = 0; i < NBF; i++) {
            int f = tid + i * 256;
            int r = f / (BN / 4);
            int c = (f % (BN / 4)) * 4;
            float4 v = *(const float4*)(W + (size_t)(k0 + r) * CO + col0 + c);
            *(float4*)&Bs[r * BSTR + c] = v;
        }
        __syncthreads();
#pragma unroll
        for (int ks = 0; ks < 4; ks++) {
            const int kb = ks * 8;
            uint32_t ah[2][4], al[2][4];
#pragma unroll
            for (int t = 0; t < 2; t++) {
                int r = warpM * 32 + t * 16 + g;
                float v0 = As[r * ASTR + kb + kk];
                float v1 = As[(r + 8) * ASTR + kb + kk];
                float v2 = As[r * ASTR + kb + kk + 4];
                float v3 = As[(r + 8) * ASTR + kb + kk + 4];
                split_tf32(v0, ah[t][0], al[t][0]);
                split_tf32(v1, ah[t][1], al[t][1]);
                split_tf32(v2, ah[t][2], al[t][2]);
                split_tf32(v3, ah[t][3], al[t][3]);
            }
#pragma unroll
            for (int j = 0; j < NT; j++) {
                int n = warpN * WN + j * 8 + g;
                float b0f = Bs[(kb + kk) * BSTR + n];
                float b1f = Bs[(kb + kk + 4) * BSTR + n];
                uint32_t b0h, b0l, b1h, b1l;
                split_tf32(b0f, b0h, b0l);
                split_tf32(b1f, b1h, b1l);
                // hi*hi + lo*hi + hi*lo  (3xTF32)
                mma_tf32(acc[0][j], ah[0], b0h, b1h);
                mma_tf32(acc[1][j], ah[1], b0h, b1h);
                mma_tf32(acc[0][j], al[0], b0h, b1h);
                mma_tf32(acc[1][j], al[1], b0h, b1h);
                mma_tf32(acc[0][j], ah[0], b0l, b1l);
                mma_tf32(acc[1][j], ah[1], b0l, b1l);
            }
        }
        __syncthreads();
    }

    // epilogue
#pragma unroll
    for (int t = 0; t < 2; t++) {
        const int r = row0 + warpM * 32 + t * 16 + g;
        float s1 = 0.f, s2 = 0.f;
        if (EPI == 0) {
            float d1 = g_dis[r], d2 = g_dis[r + 8];
            s1 = d1 * d1; s2 = d2 * d2;
        }
#pragma unroll
        for (int j = 0; j < NT; j++) {
            const int c = col0 + warpN * WN + j * 8 + 2 * kk;
            float2 v1 = make_float2(acc[t][j][0], acc[t][j][1]);
            float2 v2 = make_float2(acc[t][j][2], acc[t][j][3]);
            if (EPI == 0) {
                *(float2*)(out + (size_t)r * CO + c) = v1;
                *(float2*)(out + (size_t)(r + 8) * CO + c) = v2;
                *(float2*)(self_out + (size_t)r * CO + c) = make_float2(v1.x * s1, v1.y * s1);
                *(float2*)(self_out + (size_t)(r + 8) * CO + c) = make_float2(v2.x * s2, v2.y * s2);
            } else {
                float2 bb = *(const float2*)(bias + c);
                v1.x = fmaxf(v1.x + bb.x, 0.f);
                v1.y = fmaxf(v1.y + bb.y, 0.f);
                v2.x = fmaxf(v2.x + bb.x, 0.f);
                v2.y = fmaxf(v2.y + bb.y, 0.f);
                *(float2*)(out + (size_t)r * CO + c) = v1;
                *(float2*)(out + (size_t)(r + 8) * CO + c) = v2;
            }
        }
    }
}

// ---------------- fp32 GEMM (layer 4: 64 -> 32) ----------------
template<int BN_T, int TN_T, int EPI, bool AFFINE>
__global__ __launch_bounds__(256, 2)
void gemm_kernel(const float* __restrict__ A, const float* __restrict__ W,
                 const float* __restrict__ bias, float* __restrict__ out,
                 float* __restrict__ self_out, int K, int Co) {
    __shared__ float As[16][128];
    __shared__ float Ws[16][BN_T];
    __shared__ float sc_sh[256], sf_sh[256];
    int tid = threadIdx.x;
    int tx = tid & 15, ty = tid >> 4;
    int row0 = blockIdx.y * 128;
    int col0 = blockIdx.x * BN_T;
    if (AFFINE) {
        for (int i = tid; i < K; i += 256) { sc_sh[i] = g_scaleA[i]; sf_sh[i] = g_shiftA[i]; }
    }
    float acc[8][TN_T];
#pragma unroll
    for (int i = 0; i < 8; i++)
#pragma unroll
        for (int j = 0; j < TN_T; j++) acc[i][j] = 0.f;
    if (AFFINE) __syncthreads();
    for (int k0 = 0; k0 < K; k0 += 16) {
#pragma unroll
        for (int i = 0; i < 2; i++) {
            int f = tid * 2 + i;
            int r = f >> 2;
            int kq = (f & 3) * 4;
            float4 v = *(const float4*)(A + (size_t)(row0 + r) * K + k0 + kq);
            if (AFFINE) {
                v.x = fmaf(v.x, sc_sh[k0 + kq + 0], sf_sh[k0 + kq + 0]);
                v.y = fmaf(v.y, sc_sh[k0 + kq + 1], sf_sh[k0 + kq + 1]);
                v.z = fmaf(v.z, sc_sh[k0 + kq + 2], sf_sh[k0 + kq + 2]);
                v.w = fmaf(v.w, sc_sh[k0 + kq + 3], sf_sh[k0 + kq + 3]);
            }
            As[kq + 0][r] = v.x; As[kq + 1][r] = v.y;
            As[kq + 2][r] = v.z; As[kq + 3][r] = v.w;
        }
        {
            const int NF4 = 16 * BN_T / 4;
#pragma unroll
            for (int i = 0; i < (NF4 + 255) / 256; i++) {
                int f = tid + i * 256;
                if ((NF4 % 256 == 0) || f < NF4) {
                    int k = f / (BN_T / 4);
                    int c = (f % (BN_T / 4)) * 4;
                    float4 v = *(const float4*)(W + (size_t)(k0 + k) * Co + col0 + c);
                    Ws[k][c + 0] = v.x; Ws[k][c + 1] = v.y;
                    Ws[k][c + 2] = v.z; Ws[k][c + 3] = v.w;
                }
            }
        }
        __syncthreads();
#pragma unroll
        for (int kk = 0; kk < 16; kk++) {
            float a[8], w[TN_T];
            float4 a0 = *(const float4*)&As[kk][ty * 4];
            float4 a1 = *(const float4*)&As[kk][64 + ty * 4];
            a[0] = a0.x; a[1] = a0.y; a[2] = a0.z; a[3] = a0.w;
            a[4] = a1.x; a[5] = a1.y; a[6] = a1.z; a[7] = a1.w;
            if (TN_T == 4) {
                float4 w0 = *(const float4*)&Ws[kk][tx * 4];
                w[0] = w0.x; w[1] = w0.y; w[2] = w0.z; w[3] = w0.w;
            } else {
                float2 w0 = *(const float2*)&Ws[kk][tx * 2];
                w[0] = w0.x; w[1] = w0.y;
            }
#pragma unroll
            for (int i = 0; i < 8; i++)
#pragma unroll
                for (int j = 0; j < TN_T; j++) acc[i][j] = fmaf(a[i], w[j], acc[i][j]);
        }
        __syncthreads();
    }
#pragma unroll
    for (int i = 0; i < 8; i++) {
        int r = row0 + ((i < 4) ? (ty * 4 + i) : (64 + ty * 4 + i - 4));
        if (EPI == 0) {
            float d = g_dis[r];
            float s = d * d;
            if (TN_T >= 4) {
                int c = col0 + tx * 4;
                float4 v = make_float4(acc[i][0], acc[i][1], acc[i][2], acc[i][3]);
                *(float4*)(out + (size_t)r * Co + c) = v;
                float4 sv = make_float4(v.x * s, v.y * s, v.z * s, v.w * s);
                *(float4*)(self_out + (size_t)r * Co + c) = sv;
            } else {
                int c = col0 + tx * 2;
                float2 v = make_float2(acc[i][0], acc[i][1]);
                *(float2*)(out + (size_t)r * Co + c) = v;
                float2 sv = make_float2(v.x * s, v.y * s);
                *(float2*)(self_out + (size_t)r * Co + c) = sv;
            }
        }
    }
}

// ---------------- aggregation ----------------
template<int C>
__global__ void self_init_affine_kernel(const float* __restrict__ y, float* __restrict__ agg) {
    const int c4n = C / 4;
    int idx = blockIdx.x * blockDim.x + threadIdx.x;
    int total = N_NODES * c4n;
    if (idx >= total) return;
    int row = idx / c4n;
    int cc = idx % c4n;
    float d = g_dis[row];
    float s = d * d;
    float4 v  = ((const float4*)y)[idx];
    float4 sc = ((const float4*)g_scaleA)[cc];
    float4 sf = ((const float4*)g_shiftA)[cc];
    float4 o;
    o.x = fmaf(v.x, sc.x, sf.x) * s;
    o.y = fmaf(v.y, sc.y, sf.y) * s;
    o.z = fmaf(v.z, sc.z, sf.z) * s;
    o.w = fmaf(v.w, sc.w, sf.w) * s;
    ((float4*)agg)[idx] = o;
}

template<int C, bool AFFINE>
__global__ void edge_agg_kernel(const int* __restrict__ ei, const float* __restrict__ z,
                                float* __restrict__ agg) {
    const int c4n = C / 4;
    const int EPW = 32 / c4n;
    int warp = (blockIdx.x * blockDim.x + threadIdx.x) >> 5;
    int lane = threadIdx.x & 31;
    int sub = lane / c4n;
    int cc  = lane % c4n;
    long long e = (long long)warp * EPW + sub;
    if (e >= N_EDGES) return;
    int src = ei[e];
    int dst = ei[N_EDGES + e];
    float nrm = g_dis[src] * g_dis[dst];
    float4 v = *((const float4*)(z + (size_t)src * C) + cc);
    float4 o;
    if (AFFINE) {
        float4 sc = ((const float4*)g_scaleA)[cc];
        float4 sf = ((const float4*)g_shiftA)[cc];
        o.x = fmaf(v.x, sc.x, sf.x) * nrm;
        o.y = fmaf(v.y, sc.y, sf.y) * nrm;
        o.z = fmaf(v.z, sc.z, sf.z) * nrm;
        o.w = fmaf(v.w, sc.w, sf.w) * nrm;
    } else {
        o.x = v.x * nrm; o.y = v.y * nrm; o.z = v.z * nrm; o.w = v.w * nrm;
    }
    float4* ad = (float4*)(agg + (size_t)dst * C) + cc;
    asm volatile("red.global.add.v4.f32 [%0], {%1, %2, %3, %4};"
                 :: "l"(ad), "f"(o.x), "f"(o.y), "f"(o.z), "f"(o.w)
                 : "memory");
}

// ---------------- fused combine + relu + BN-stats ----------------
__global__ void zero_stats_kernel() {
    int i = threadIdx.x;
    if (i < MAXC) { g_sum[i] = 0.0; g_sumsq[i] = 0.0; }
}

template<int C>
__global__ void combine_stats_kernel(const float* __restrict__ agg, const float* __restrict__ b,
                                     float* __restrict__ y) {
    const int c4n = C / 4;
    const int ROWS = 256 / c4n;
    int cc = threadIdx.x % c4n;
    int rg = threadIdx.x / c4n;
    float4 bb = ((const float4*)b)[cc];
    float s[4] = {0, 0, 0, 0}, q[4] = {0, 0, 0, 0};
    for (int r = blockIdx.x * ROWS + rg; r < N_NODES; r += gridDim.x * ROWS) {
        float4 v = *((const float4*)(agg + (size_t)r * C) + cc);
        v.x = fmaxf(v.x + bb.x, 0.f);
        v.y = fmaxf(v.y + bb.y, 0.f);
        v.z = fmaxf(v.z + bb.z, 0.f);
        v.w = fmaxf(v.w + bb.w, 0.f);
        *((float4*)(y + (size_t)r * C) + cc) = v;
        s[0] += v.x; q[0] += v.x * v.x;
        s[1] += v.y; q[1] += v.y * v.y;
        s[2] += v.z; q[2] += v.z * v.z;
        s[3] += v.w; q[3] += v.w * v.w;
    }
    __shared__ float shs[256 * 4], shq[256 * 4];
#pragma unroll
    for (int j = 0; j < 4; j++) { shs[threadIdx.x * 4 + j] = s[j]; shq[threadIdx.x * 4 + j] = q[j]; }
    __syncthreads();
    if (rg == 0) {
#pragma unroll 1
        for (int g = 1; g < ROWS; g++) {
            int base = (g * c4n + cc) * 4;
#pragma unroll
            for (int j = 0; j < 4; j++) { s[j] += shs[base + j]; q[j] += shq[base + j]; }
        }
#pragma unroll
        for (int j = 0; j < 4; j++) {
            atomicAdd(&g_sum[cc * 4 + j],   (double)s[j]);
            atomicAdd(&g_sumsq[cc * 4 + j], (double)q[j]);
        }
    }
}

template<int C>
__global__ void stats_only_kernel(const float* __restrict__ y) {
    const int c4n = C / 4;
    const int ROWS = 256 / c4n;
    int cc = threadIdx.x % c4n;
    int rg = threadIdx.x / c4n;
    float s[4] = {0, 0, 0, 0}, q[4] = {0, 0, 0, 0};
    for (int r = blockIdx.x * ROWS + rg; r < N_NODES; r += gridDim.x * ROWS) {
        float4 v = *((const float4*)(y + (size_t)r * C) + cc);
        s[0] += v.x; q[0] += v.x * v.x;
        s[1] += v.y; q[1] += v.y * v.y;
        s[2] += v.z; q[2] += v.z * v.z;
        s[3] += v.w; q[3] += v.w * v.w;
    }
    __shared__ float shs[256 * 4], shq[256 * 4];
#pragma unroll
    for (int j = 0; j < 4; j++) { shs[threadIdx.x * 4 + j] = s[j]; shq[threadIdx.x * 4 + j] = q[j]; }
    __syncthreads();
    if (rg == 0) {
#pragma unroll 1
        for (int g = 1; g < ROWS; g++) {
            int base = (g * c4n + cc) * 4;
#pragma unroll
            for (int j = 0; j < 4; j++) { s[j] += shs[base + j]; q[j] += shq[base + j]; }
        }
#pragma unroll
        for (int j = 0; j < 4; j++) {
            atomicAdd(&g_sum[cc * 4 + j],   (double)s[j]);
            atomicAdd(&g_sumsq[cc * 4 + j], (double)q[j]);
        }
    }
}

__global__ void stats_c1_kernel(const float* __restrict__ v) {
    float s = 0.f, q = 0.f;
    for (int i = blockIdx.x * 256 + threadIdx.x; i < N_NODES; i += gridDim.x * 256) {
        float x = v[i];
        s += x; q += x * x;
    }
    __shared__ float shs[256], shq[256];
    shs[threadIdx.x] = s; shq[threadIdx.x] = q;
    __syncthreads();
    for (int o = 128; o; o >>= 1) {
        if (threadIdx.x < o) { shs[threadIdx.x] += shs[threadIdx.x + o]; shq[threadIdx.x] += shq[threadIdx.x + o]; }
        __syncthreads();
    }
    if (threadIdx.x == 0) {
        atomicAdd(&g_sum[0],   (double)shs[0]);
        atomicAdd(&g_sumsq[0], (double)shq[0]);
    }
}

__global__ void bn_finalize_kernel(const float* __restrict__ gam, const float* __restrict__ bet,
                                   int C, float* __restrict__ oS, float* __restrict__ oH) {
    int c = threadIdx.x;
    if (c >= C) return;
    double mean = g_sum[c] / (double)N_NODES;
    double var = g_sumsq[c] / (double)N_NODES - mean * mean;
    double sc = (double)gam[c] / sqrt(var + (double)BN_EPS);
    oS[c] = (float)sc;
    oH[c] = bet[c] - (float)(mean * sc);
}

// ---------------- gate network ----------------
__global__ void gate1_kernel(const float* __restrict__ y4, const float* __restrict__ gW1,
                             const float* __restrict__ gb1, float* __restrict__ outz) {
    __shared__ float w[32 * 16];
    __shared__ float bb[16], sc[32], sf[32];
    int tid = threadIdx.x;
    for (int i = tid; i < 512; i += 256) w[i] = gW1[i];
    if (tid < 16) bb[tid] = gb1[tid];
    if (tid < 32) { sc[tid] = g_scale4[tid]; sf[tid] = g_shift4[tid]; }
    __syncthreads();
    int row = blockIdx.x * 256 + tid;
    float h[32];
#pragma unroll
    for (int k4 = 0; k4 < 8; k4++) {
        float4 v = *((const float4*)(y4 + (size_t)row * 32) + k4);
        h[k4 * 4 + 0] = fmaf(v.x, sc[k4 * 4 + 0], sf[k4 * 4 + 0]);
        h[k4 * 4 + 1] = fmaf(v.y, sc[k4 * 4 + 1], sf[k4 * 4 + 1]);
        h[k4 * 4 + 2] = fmaf(v.z, sc[k4 * 4 + 2], sf[k4 * 4 + 2]);
        h[k4 * 4 + 3] = fmaf(v.w, sc[k4 * 4 + 3], sf[k4 * 4 + 3]);
    }
    float acc[16];
#pragma unroll
    for (int j = 0; j < 16; j++) acc[j] = bb[j];
#pragma unroll
    for (int k = 0; k < 32; k++)
#pragma unroll
        for (int j = 0; j < 16; j++) acc[j] = fmaf(h[k], w[k * 16 + j], acc[j]);
#pragma unroll
    for (int j4 = 0; j4 < 4; j4++)
        *((float4*)(outz + (size_t)row * 16) + j4) =
            make_float4(acc[j4 * 4], acc[j4 * 4 + 1], acc[j4 * 4 + 2], acc[j4 * 4 + 3]);
}

__global__ void gate2_kernel(const float* __restrict__ z, const float* __restrict__ gW2,
                             const float* __restrict__ gb2, float* __restrict__ out) {
    __shared__ float w[16], sc[16], sf[16], b0;
    int tid = threadIdx.x;
    if (tid < 16) { w[tid] = gW2[tid]; sc[tid] = g_scaleG1[tid]; sf[tid] = g_shiftG1[tid]; }
    if (tid == 0) b0 = gb2[0];
    __syncthreads();
    int row = blockIdx.x * 256 + tid;
    float acc = b0;
#pragma unroll
    for (int k4 = 0; k4 < 4; k4++) {
        float4 v = *((const float4*)(z + (size_t)row * 16) + k4);
        acc = fmaf(fmaxf(fmaf(v.x, sc[k4 * 4 + 0], sf[k4 * 4 + 0]), 0.f), w[k4 * 4 + 0], acc);
        acc = fmaf(fmaxf(fmaf(v.y, sc[k4 * 4 + 1], sf[k4 * 4 + 1]), 0.f), w[k4 * 4 + 1], acc);
        acc = fmaf(fmaxf(fmaf(v.z, sc[k4 * 4 + 2], sf[k4 * 4 + 2]), 0.f), w[k4 * 4 + 2], acc);
        acc = fmaf(fmaxf(fmaf(v.w, sc[k4 * 4 + 3], sf[k4 * 4 + 3]), 0.f), w[k4 * 4 + 3], acc);
    }
    out[row] = acc;
}

// ---------------- pooling + FC + softmax ----------------
__global__ void pool_fc_kernel(const float* __restrict__ y4, const float* __restrict__ g2,
                               const float* __restrict__ fcW, const float* __restrict__ fcb,
                               float* __restrict__ out) {
    int warp = (blockIdx.x * blockDim.x + threadIdx.x) >> 5;
    int lane = threadIdx.x & 31;
    if (warp >= NGRAPH) return;
    int n0 = warp * ONE_STEP;
    const unsigned FULL = 0xffffffffu;
    float scG = g_scaleG2[0], sfG = g_shiftG2[0];
    float gv = (lane < ONE_STEP) ? fmaxf(fmaf(g2[n0 + lane], scG, sfG), 0.f) : -INFINITY;
    float m = gv;
#pragma unroll
    for (int o = 16; o; o >>= 1) m = fmaxf(m, __shfl_xor_sync(FULL, m, o));
    float ev = (lane < ONE_STEP) ? expf(gv - m) : 0.f;
    float s = ev;
#pragma unroll
    for (int o = 16; o; o >>= 1) s += __shfl_xor_sync(FULL, s, o);
    float inv = 1.0f / s;
    float sc4 = g_scale4[lane], sf4 = g_shift4[lane];
    float pooled = 0.f;
#pragma unroll
    for (int i = 0; i < ONE_STEP; i++) {
        float a = __shfl_sync(FULL, ev, i) * inv;
        float hv = fmaf(y4[(size_t)(n0 + i) * 32 + lane], sc4, sf4);
        pooled = fmaf(a, hv, pooled);
    }
    float logits[10];
#pragma unroll
    for (int j = 0; j < 10; j++) {
        float p = pooled * fcW[lane * 10 + j];
#pragma unroll
        for (int o = 16; o; o >>= 1) p += __shfl_xor_sync(FULL, p, o);
        logits[j] = p + fcb[j];
    }
    if (lane == 0) {
        float mx = logits[0];
#pragma unroll
        for (int j = 1; j < 10; j++) mx = fmaxf(mx, logits[j]);
        float ss = 0.f;
        float e[10];
#pragma unroll
        for (int j = 0; j < 10; j++) { e[j] = expf(logits[j] - mx); ss += e[j]; }
        float invs = 1.0f / ss;
#pragma unroll
        for (int j = 0; j < 10; j++) out[warp * 10 + j] = e[j] * invs;
    }
}

// ---------------- host orchestration ----------------
extern "C" void kernel_launch(void* const* d_in, const int* in_sizes, int n_in,
                              void* d_out, int out_size) {
    const float* x    = (const float*)d_in[0];
    const int*   ei   = (const int*)d_in[1];
    const float* W1   = (const float*)d_in[2];
    const float* b1   = (const float*)d_in[3];
    const float* bn1g = (const float*)d_in[4];
    const float* bn1b = (const float*)d_in[5];
    const float* W2   = (const float*)d_in[6];
    const float* b2   = (const float*)d_in[7];
    const float* bn2g = (const float*)d_in[8];
    const float* bn2b = (const float*)d_in[9];
    const float* W3   = (const float*)d_in[10];
    const float* b3   = (const float*)d_in[11];
    const float* bn3g = (const float*)d_in[12];
    const float* bn3b = (const float*)d_in[13];
    const float* W4   = (const float*)d_in[14];
    const float* b4   = (const float*)d_in[15];
    const float* bn4g = (const float*)d_in[16];
    const float* bn4b = (const float*)d_in[17];
    const float* gW1  = (const float*)d_in[18];
    const float* gb1  = (const float*)d_in[19];
    const float* gbn1g = (const float*)d_in[20];
    const float* gbn1b = (const float*)d_in[21];
    const float* gW2  = (const float*)d_in[22];
    const float* gb2  = (const float*)d_in[23];
    const float* gbn2g = (const float*)d_in[24];
    const float* gbn2b = (const float*)d_in[25];
    const float* fcW  = (const float*)d_in[26];
    const float* fcb  = (const float*)d_in[27];
    float* out = (float*)d_out;

    float *buf0, *buf1, *buf2;
    float *scA, *shA, *sc4, *sh4, *scG1, *shG1, *scG2, *shG2;
    cudaGetSymbolAddress((void**)&buf0, g_buf0);
    cudaGetSymbolAddress((void**)&buf1, g_buf1);
    cudaGetSymbolAddress((void**)&buf2, g_buf2);
    cudaGetSymbolAddress((void**)&scA, g_scaleA);
    cudaGetSymbolAddress((void**)&shA, g_shiftA);
    cudaGetSymbolAddress((void**)&sc4, g_scale4);
    cudaGetSymbolAddress((void**)&sh4, g_shift4);
    cudaGetSymbolAddress((void**)&scG1, g_scaleG1);
    cudaGetSymbolAddress((void**)&shG1, g_shiftG1);
    cudaGetSymbolAddress((void**)&scG2, g_scaleG2);
    cudaGetSymbolAddress((void**)&shG2, g_shiftG2);

    const int GRID = N_NODES / 128;  // 896
    const int SM_L1 = (2 * 128 * 36 + 2 * 32 * 136) * 4;            // 71680
    const int SM_L2 = (2 * 128 * 36 + 2 * 32 * 136) * 4;            // 71680
    const int SM_L3 = (2 * 128 * 36 + 2 * 32 * 72 + 2 * 256) * 4;   // 57344
    cudaFuncSetAttribute((const void*)mma_gemm_kernel<128, 128, 512, false, 0>,
                         cudaFuncAttributeMaxDynamicSharedMemorySize, SM_L1);
    cudaFuncSetAttribute((const void*)mma_gemm_kernel<256, 128, 128, false, 1>,
                         cudaFuncAttributeMaxDynamicSharedMemorySize, SM_L2);
    cudaFuncSetAttribute((const void*)mma_gemm_kernel<64, 64, 256, true, 0>,
                         cudaFuncAttributeMaxDynamicSharedMemorySize, SM_L3);

    // degree / rsqrt normalization
    deg_zero_kernel<<<(N_NODES + 255) / 256, 256>>>();
    deg_count_kernel<<<(N_EDGES + 255) / 256, 256>>>(ei);
    deg_rsqrt_kernel<<<(N_NODES + 255) / 256, 256>>>();

    // ---- Layer 1 (512 -> 128): 3xTF32 mma GEMM, then aggregate ----
    mma_gemm_kernel<128, 128, 512, false, 0><<<dim3(1, GRID), 256, SM_L1>>>(x, W1, nullptr, buf1, buf2);
    edge_agg_kernel<128, false><<<N_EDGES / 8, 256>>>(ei, buf1, buf2);
    zero_stats_kernel<<<1, 256>>>();
    combine_stats_kernel<128><<<512, 256>>>(buf2, b1, buf0);
    bn_finalize_kernel<<<1, 128>>>(bn1g, bn1b, 128, scA, shA);

    // ---- Layer 2 (128 -> 256): aggregate first (BN fused), 3xTF32 GEMM + relu ----
    self_init_affine_kernel<128><<<(N_NODES * 32 + 255) / 256, 256>>>(buf0, buf2);
    edge_agg_kernel<128, true><<<N_EDGES / 8, 256>>>(ei, buf0, buf2);
    mma_gemm_kernel<256, 128, 128, false, 1><<<dim3(2, GRID), 256, SM_L2>>>(buf2, W2, b2, buf0, nullptr);
    zero_stats_kernel<<<1, 256>>>();
    stats_only_kernel<256><<<512, 256>>>(buf0);
    bn_finalize_kernel<<<1, 256>>>(bn2g, bn2b, 256, scA, shA);

    // ---- Layer 3 (256 -> 64): 3xTF32 GEMM (BN fused into A load), aggregate ----
    mma_gemm_kernel<64, 64, 256, true, 0><<<dim3(1, GRID), 256, SM_L3>>>(buf0, W3, nullptr, buf1, buf2);
    edge_agg_kernel<64, false><<<N_EDGES / 16, 256>>>(ei, buf1, buf2);
    zero_stats_kernel<<<1, 256>>>();
    combine_stats_kernel<64><<<512, 256>>>(buf2, b3, buf0);
    bn_finalize_kernel<<<1, 64>>>(bn3g, bn3b, 64, scA, shA);

    // ---- Layer 4 (64 -> 32): fp32 GEMM (cheap), aggregate ----
    gemm_kernel<32, 2, 0, true><<<dim3(1, GRID), 256>>>(buf0, W4, nullptr, buf1, buf2, 64, 32);
    edge_agg_kernel<32, false><<<N_EDGES / 32, 256>>>(ei, buf1, buf2);
    zero_stats_kernel<<<1, 256>>>();
    combine_stats_kernel<32><<<512, 256>>>(buf2, b4, buf0);
    bn_finalize_kernel<<<1, 32>>>(bn4g, bn4b, 32, sc4, sh4);

    // ---- gate layer 1 ----
    gate1_kernel<<<N_NODES / 256, 256>>>(buf0, gW1, gb1, buf1);
    zero_stats_kernel<<<1, 256>>>();
    stats_only_kernel<16><<<512, 256>>>(buf1);
    bn_finalize_kernel<<<1, 16>>>(gbn1g, gbn1b, 16, scG1, shG1);

    // ---- gate layer 2 ----
    gate2_kernel<<<N_NODES / 256, 256>>>(buf1, gW2, gb2, buf2);
    zero_stats_kernel<<<1, 256>>>();
    stats_c1_kernel<<<128, 256>>>(buf2);
    bn_finalize_kernel<<<1, 32>>>(gbn2g, gbn2b, 1, scG2, shG2);

    // ---- segment softmax pooling + FC + softmax ----
    pool_fc_kernel<<<(NGRAPH * 32 + 255) / 256, 256>>>(buf0, buf2, fcW, fcb, out);
}

// round 8
// speedup vs baseline: 1.1633x; 1.1633x over previous
#include <cuda_runtime.h>
#include <math.h>
#include <stdint.h>

#define N_NODES 114688
#define N_EDGES 917504
#define MAXC    256
#define BN_EPS  1e-5f
#define ONE_STEP 14
#define NGRAPH  (N_NODES / ONE_STEP)

// ---------------- scratch (static device globals; no allocation) ----------------
__device__ __align__(16) float  g_buf0[(size_t)N_NODES * MAXC];
__device__ __align__(16) float  g_buf1[(size_t)N_NODES * MAXC];
__device__ __align__(16) float  g_buf2[(size_t)N_NODES * MAXC];
__device__ float  g_dis[N_NODES];
__device__ double g_sum[MAXC], g_sumsq[MAXC];
__device__ __align__(16) float g_scaleA[MAXC], g_shiftA[MAXC];
__device__ __align__(16) float g_scale4[32],  g_shift4[32];
__device__ __align__(16) float g_scaleG1[16], g_shiftG1[16];
__device__ __align__(16) float g_scaleG2[4],  g_shiftG2[4];

__device__ __forceinline__ uint32_t f2tf32(float x) {
    uint32_t r;
    asm("cvt.rna.tf32.f32 %0, %1;" : "=r"(r) : "f"(x));
    return r;
}
// split-precision: v = hi + lo with both representable in tf32
__device__ __forceinline__ void split_tf32(float v, uint32_t& hi, uint32_t& lo) {
    hi = f2tf32(v);
    lo = f2tf32(v - __uint_as_float(hi));
}
__device__ __forceinline__ void mma_tf32(float* c, const uint32_t* a, uint32_t b0, uint32_t b1) {
    asm volatile(
        "mma.sync.aligned.m16n8k8.row.col.f32.tf32.tf32.f32 "
        "{%0,%1,%2,%3}, {%4,%5,%6,%7}, {%8,%9}, {%0,%1,%2,%3};"
        : "+f"(c[0]), "+f"(c[1]), "+f"(c[2]), "+f"(c[3])
        : "r"(a[0]), "r"(a[1]), "r"(a[2]), "r"(a[3]), "r"(b0), "r"(b1));
}

// ---------------- degree / normalization ----------------
__global__ void deg_zero_kernel() {
    int i = blockIdx.x * blockDim.x + threadIdx.x;
    if (i < N_NODES) g_dis[i] = 0.f;
}
__global__ void deg_count_kernel(const int* __restrict__ ei) {
    int e = blockIdx.x * blockDim.x + threadIdx.x;
    if (e < N_EDGES) atomicAdd(&g_dis[ei[N_EDGES + e]], 1.0f);
}
__global__ void deg_rsqrt_kernel() {
    int i = blockIdx.x * blockDim.x + threadIdx.x;
    if (i < N_NODES) g_dis[i] = rsqrtf(g_dis[i] + 1.0f);
}

// ---------------- 3xTF32 mma.sync GEMM, split-at-load ----------------
// C[N,CO] = A'[N,K] @ W[K,CO]; A' = A (or BN affine). Block tile 128 x BN.
// 8 warps (4M x 2N), warp tile 32 x BN/2, BK=32.
// hi/lo tf32 split done ONCE at smem-store; inner loop is pure LDS+MMA.
// Single-buffered smem; 2 CTAs/SM via launch_bounds hide the load phase.
// EPI 0: out=z, self_out=dis^2*z.  EPI 1: out=relu(z+bias).
template<int CO, int BN, int K, bool AFFINE, int EPI>
__global__ __launch_bounds__(256, 2)
void mma_gemm_kernel(const float* __restrict__ A, const float* __restrict__ W,
                     const float* __restrict__ bias, float* __restrict__ out,
                     float* __restrict__ self_out) {
    const int ASTR = 36;            // 128x32 A tile rows, padded
    const int BSTR = BN + 8;        // 32xBN B tile rows, padded
    const int AW = 128 * ASTR;
    const int BW = 32 * BSTR;
    extern __shared__ uint32_t sm[];
    uint32_t* const Ah = sm;
    uint32_t* const Al = sm + AW;
    uint32_t* const Bh = sm + 2 * AW;
    uint32_t* const Bl = sm + 2 * AW + BW;
    float* const scs = (float*)(sm + 2 * AW + 2 * BW);
    float* const sfs = scs + K;

    const int tid = threadIdx.x;
    const int lane = tid & 31, wid = tid >> 5;
    const int warpM = wid & 3, warpN = wid >> 2;
    const int WN = BN / 2;
    const int NT = WN / 8;
    const int g = lane >> 2, kk = lane & 3;
    const int row0 = blockIdx.y * 128;
    const int col0 = blockIdx.x * BN;

    if (AFFINE) {
        for (int i = tid; i < K; i += 256) { scs[i] = g_scaleA[i]; sfs[i] = g_shiftA[i]; }
        __syncthreads();
    }

    float acc[2][NT][4];
#pragma unroll
    for (int t = 0; t < 2; t++)
#pragma unroll
        for (int j = 0; j < NT; j++)
#pragma unroll
            for (int q = 0; q < 4; q++) acc[t][j][q] = 0.f;

    const int NCH = K / 32;
    for (int ch = 0; ch < NCH; ch++) {
        const int k0 = ch * 32;
        if (ch) __syncthreads();   // previous compute done before overwrite
        // A tile: 128 rows x 32 k -> split hi/lo at store
#pragma unroll
        for (int i = 0; i < 4; i++) {
            int f = tid + i * 256;
            int r = f >> 3;
            int kq = (f & 7) * 4;
            float4 v = *(const float4*)(A + (size_t)(row0 + r) * K + k0 + kq);
            if (AFFINE) {
                v.x = fmaf(v.x, scs[k0 + kq + 0], sfs[k0 + kq + 0]);
                v.y = fmaf(v.y, scs[k0 + kq + 1], sfs[k0 + kq + 1]);
                v.z = fmaf(v.z, scs[k0 + kq + 2], sfs[k0 + kq + 2]);
                v.w = fmaf(v.w, scs[k0 + kq + 3], sfs[k0 + kq + 3]);
            }
            uint4 h4, l4;
            split_tf32(v.x, h4.x, l4.x);
            split_tf32(v.y, h4.y, l4.y);
            split_tf32(v.z, h4.z, l4.z);
            split_tf32(v.w, h4.w, l4.w);
            *(uint4*)&Ah[r * ASTR + kq] = h4;
            *(uint4*)&Al[r * ASTR + kq] = l4;
        }
        // B tile: 32 rows x BN cols -> split hi/lo at store
        const int NBF = 32 * BN / 4 / 256;
#pragma unroll
        for (int i = 0; i < NBF; i++) {
            int f = tid + i * 256;
            int r = f / (BN / 4);
            int c = (f % (BN / 4)) * 4;
            float4 v = *(const float4*)(W + (size_t)(k0 + r) * CO + col0 + c);
            uint4 h4, l4;
            split_tf32(v.x, h4.x, l4.x);
            split_tf32(v.y, h4.y, l4.y);
            split_tf32(v.z, h4.z, l4.z);
            split_tf32(v.w, h4.w, l4.w);
            *(uint4*)&Bh[r * BSTR + c] = h4;
            *(uint4*)&Bl[r * BSTR + c] = l4;
        }
        __syncthreads();
#pragma unroll
        for (int ks = 0; ks < 4; ks++) {
            const int kb = ks * 8;
            uint32_t ah[2][4], al[2][4];
#pragma unroll
            for (int t = 0; t < 2; t++) {
                int r = warpM * 32 + t * 16 + g;
                ah[t][0] = Ah[r * ASTR + kb + kk];
                ah[t][1] = Ah[(r + 8) * ASTR + kb + kk];
                ah[t][2] = Ah[r * ASTR + kb + kk + 4];
                ah[t][3] = Ah[(r + 8) * ASTR + kb + kk + 4];
                al[t][0] = Al[r * ASTR + kb + kk];
                al[t][1] = Al[(r + 8) * ASTR + kb + kk];
                al[t][2] = Al[r * ASTR + kb + kk + 4];
                al[t][3] = Al[(r + 8) * ASTR + kb + kk + 4];
            }
#pragma unroll
            for (int j = 0; j < NT; j++) {
                int n = warpN * WN + j * 8 + g;
                uint32_t b0h = Bh[(kb + kk) * BSTR + n];
                uint32_t b1h = Bh[(kb + kk + 4) * BSTR + n];
                uint32_t b0l = Bl[(kb + kk) * BSTR + n];
                uint32_t b1l = Bl[(kb + kk + 4) * BSTR + n];
                // hi*hi + lo*hi + hi*lo  (3xTF32)
                mma_tf32(acc[0][j], ah[0], b0h, b1h);
                mma_tf32(acc[1][j], ah[1], b0h, b1h);
                mma_tf32(acc[0][j], al[0], b0h, b1h);
                mma_tf32(acc[1][j], al[1], b0h, b1h);
                mma_tf32(acc[0][j], ah[0], b0l, b1l);
                mma_tf32(acc[1][j], ah[1], b0l, b1l);
            }
        }
    }

    // epilogue
#pragma unroll
    for (int t = 0; t < 2; t++) {
        const int r = row0 + warpM * 32 + t * 16 + g;
        float s1 = 0.f, s2 = 0.f;
        if (EPI == 0) {
            float d1 = g_dis[r], d2 = g_dis[r + 8];
            s1 = d1 * d1; s2 = d2 * d2;
        }
#pragma unroll
        for (int j = 0; j < NT; j++) {
            const int c = col0 + warpN * WN + j * 8 + 2 * kk;
            float2 v1 = make_float2(acc[t][j][0], acc[t][j][1]);
            float2 v2 = make_float2(acc[t][j][2], acc[t][j][3]);
            if (EPI == 0) {
                *(float2*)(out + (size_t)r * CO + c) = v1;
                *(float2*)(out + (size_t)(r + 8) * CO + c) = v2;
                *(float2*)(self_out + (size_t)r * CO + c) = make_float2(v1.x * s1, v1.y * s1);
                *(float2*)(self_out + (size_t)(r + 8) * CO + c) = make_float2(v2.x * s2, v2.y * s2);
            } else {
                float2 bb = *(const float2*)(bias + c);
                v1.x = fmaxf(v1.x + bb.x, 0.f);
                v1.y = fmaxf(v1.y + bb.y, 0.f);
                v2.x = fmaxf(v2.x + bb.x, 0.f);
                v2.y = fmaxf(v2.y + bb.y, 0.f);
                *(float2*)(out + (size_t)r * CO + c) = v1;
                *(float2*)(out + (size_t)(r + 8) * CO + c) = v2;
            }
        }
    }
}

// ---------------- fp32 GEMM (layer 4: 64 -> 32) ----------------
template<int BN_T, int TN_T, int EPI, bool AFFINE>
__global__ __launch_bounds__(256, 2)
void gemm_kernel(const float* __restrict__ A, const float* __restrict__ W,
                 const float* __restrict__ bias, float* __restrict__ out,
                 float* __restrict__ self_out, int K, int Co) {
    __shared__ float As[16][128];
    __shared__ float Ws[16][BN_T];
    __shared__ float sc_sh[256], sf_sh[256];
    int tid = threadIdx.x;
    int tx = tid & 15, ty = tid >> 4;
    int row0 = blockIdx.y * 128;
    int col0 = blockIdx.x * BN_T;
    if (AFFINE) {
        for (int i = tid; i < K; i += 256) { sc_sh[i] = g_scaleA[i]; sf_sh[i] = g_shiftA[i]; }
    }
    float acc[8][TN_T];
#pragma unroll
    for (int i = 0; i < 8; i++)
#pragma unroll
        for (int j = 0; j < TN_T; j++) acc[i][j] = 0.f;
    if (AFFINE) __syncthreads();
    for (int k0 = 0; k0 < K; k0 += 16) {
#pragma unroll
        for (int i = 0; i < 2; i++) {
            int f = tid * 2 + i;
            int r = f >> 2;
            int kq = (f & 3) * 4;
            float4 v = *(const float4*)(A + (size_t)(row0 + r) * K + k0 + kq);
            if (AFFINE) {
                v.x = fmaf(v.x, sc_sh[k0 + kq + 0], sf_sh[k0 + kq + 0]);
                v.y = fmaf(v.y, sc_sh[k0 + kq + 1], sf_sh[k0 + kq + 1]);
                v.z = fmaf(v.z, sc_sh[k0 + kq + 2], sf_sh[k0 + kq + 2]);
                v.w = fmaf(v.w, sc_sh[k0 + kq + 3], sf_sh[k0 + kq + 3]);
            }
            As[kq + 0][r] = v.x; As[kq + 1][r] = v.y;
            As[kq + 2][r] = v.z; As[kq + 3][r] = v.w;
        }
        {
            const int NF4 = 16 * BN_T / 4;
#pragma unroll
            for (int i = 0; i < (NF4 + 255) / 256; i++) {
                int f = tid + i * 256;
                if ((NF4 % 256 == 0) || f < NF4) {
                    int k = f / (BN_T / 4);
                    int c = (f % (BN_T / 4)) * 4;
                    float4 v = *(const float4*)(W + (size_t)(k0 + k) * Co + col0 + c);
                    Ws[k][c + 0] = v.x; Ws[k][c + 1] = v.y;
                    Ws[k][c + 2] = v.z; Ws[k][c + 3] = v.w;
                }
            }
        }
        __syncthreads();
#pragma unroll
        for (int kk = 0; kk < 16; kk++) {
            float a[8], w[TN_T];
            float4 a0 = *(const float4*)&As[kk][ty * 4];
            float4 a1 = *(const float4*)&As[kk][64 + ty * 4];
            a[0] = a0.x; a[1] = a0.y; a[2] = a0.z; a[3] = a0.w;
            a[4] = a1.x; a[5] = a1.y; a[6] = a1.z; a[7] = a1.w;
            if (TN_T == 4) {
                float4 w0 = *(const float4*)&Ws[kk][tx * 4];
                w[0] = w0.x; w[1] = w0.y; w[2] = w0.z; w[3] = w0.w;
            } else {
                float2 w0 = *(const float2*)&Ws[kk][tx * 2];
                w[0] = w0.x; w[1] = w0.y;
            }
#pragma unroll
            for (int i = 0; i < 8; i++)
#pragma unroll
                for (int j = 0; j < TN_T; j++) acc[i][j] = fmaf(a[i], w[j], acc[i][j]);
        }
        __syncthreads();
    }
#pragma unroll
    for (int i = 0; i < 8; i++) {
        int r = row0 + ((i < 4) ? (ty * 4 + i) : (64 + ty * 4 + i - 4));
        if (EPI == 0) {
            float d = g_dis[r];
            float s = d * d;
            if (TN_T >= 4) {
                int c = col0 + tx * 4;
                float4 v = make_float4(acc[i][0], acc[i][1], acc[i][2], acc[i][3]);
                *(float4*)(out + (size_t)r * Co + c) = v;
                float4 sv = make_float4(v.x * s, v.y * s, v.z * s, v.w * s);
                *(float4*)(self_out + (size_t)r * Co + c) = sv;
            } else {
                int c = col0 + tx * 2;
                float2 v = make_float2(acc[i][0], acc[i][1]);
                *(float2*)(out + (size_t)r * Co + c) = v;
                float2 sv = make_float2(v.x * s, v.y * s);
                *(float2*)(self_out + (size_t)r * Co + c) = sv;
            }
        }
    }
}

// ---------------- aggregation ----------------
template<int C>
__global__ void self_init_affine_kernel(const float* __restrict__ y, float* __restrict__ agg) {
    const int c4n = C / 4;
    int idx = blockIdx.x * blockDim.x + threadIdx.x;
    int total = N_NODES * c4n;
    if (idx >= total) return;
    int row = idx / c4n;
    int cc = idx % c4n;
    float d = g_dis[row];
    float s = d * d;
    float4 v  = ((const float4*)y)[idx];
    float4 sc = ((const float4*)g_scaleA)[cc];
    float4 sf = ((const float4*)g_shiftA)[cc];
    float4 o;
    o.x = fmaf(v.x, sc.x, sf.x) * s;
    o.y = fmaf(v.y, sc.y, sf.y) * s;
    o.z = fmaf(v.z, sc.z, sf.z) * s;
    o.w = fmaf(v.w, sc.w, sf.w) * s;
    ((float4*)agg)[idx] = o;
}

template<int C, bool AFFINE>
__global__ void edge_agg_kernel(const int* __restrict__ ei, const float* __restrict__ z,
                                float* __restrict__ agg) {
    const int c4n = C / 4;
    const int EPW = 32 / c4n;
    int warp = (blockIdx.x * blockDim.x + threadIdx.x) >> 5;
    int lane = threadIdx.x & 31;
    int sub = lane / c4n;
    int cc  = lane % c4n;
    long long e = (long long)warp * EPW + sub;
    if (e >= N_EDGES) return;
    int src = ei[e];
    int dst = ei[N_EDGES + e];
    float nrm = g_dis[src] * g_dis[dst];
    float4 v = *((const float4*)(z + (size_t)src * C) + cc);
    float4 o;
    if (AFFINE) {
        float4 sc = ((const float4*)g_scaleA)[cc];
        float4 sf = ((const float4*)g_shiftA)[cc];
        o.x = fmaf(v.x, sc.x, sf.x) * nrm;
        o.y = fmaf(v.y, sc.y, sf.y) * nrm;
        o.z = fmaf(v.z, sc.z, sf.z) * nrm;
        o.w = fmaf(v.w, sc.w, sf.w) * nrm;
    } else {
        o.x = v.x * nrm; o.y = v.y * nrm; o.z = v.z * nrm; o.w = v.w * nrm;
    }
    float4* ad = (float4*)(agg + (size_t)dst * C) + cc;
    asm volatile("red.global.add.v4.f32 [%0], {%1, %2, %3, %4};"
                 :: "l"(ad), "f"(o.x), "f"(o.y), "f"(o.z), "f"(o.w)
                 : "memory");
}

// ---------------- fused combine + relu + BN-stats ----------------
__global__ void zero_stats_kernel() {
    int i = threadIdx.x;
    if (i < MAXC) { g_sum[i] = 0.0; g_sumsq[i] = 0.0; }
}

template<int C>
__global__ void combine_stats_kernel(const float* __restrict__ agg, const float* __restrict__ b,
                                     float* __restrict__ y) {
    const int c4n = C / 4;
    const int ROWS = 256 / c4n;
    int cc = threadIdx.x % c4n;
    int rg = threadIdx.x / c4n;
    float4 bb = ((const float4*)b)[cc];
    float s[4] = {0, 0, 0, 0}, q[4] = {0, 0, 0, 0};
    for (int r = blockIdx.x * ROWS + rg; r < N_NODES; r += gridDim.x * ROWS) {
        float4 v = *((const float4*)(agg + (size_t)r * C) + cc);
        v.x = fmaxf(v.x + bb.x, 0.f);
        v.y = fmaxf(v.y + bb.y, 0.f);
        v.z = fmaxf(v.z + bb.z, 0.f);
        v.w = fmaxf(v.w + bb.w, 0.f);
        *((float4*)(y + (size_t)r * C) + cc) = v;
        s[0] += v.x; q[0] += v.x * v.x;
        s[1] += v.y; q[1] += v.y * v.y;
        s[2] += v.z; q[2] += v.z * v.z;
        s[3] += v.w; q[3] += v.w * v.w;
    }
    __shared__ float shs[256 * 4], shq[256 * 4];
#pragma unroll
    for (int j = 0; j < 4; j++) { shs[threadIdx.x * 4 + j] = s[j]; shq[threadIdx.x * 4 + j] = q[j]; }
    __syncthreads();
    if (rg == 0) {
#pragma unroll 1
        for (int g = 1; g < ROWS; g++) {
            int base = (g * c4n + cc) * 4;
#pragma unroll
            for (int j = 0; j < 4; j++) { s[j] += shs[base + j]; q[j] += shq[base + j]; }
        }
#pragma unroll
        for (int j = 0; j < 4; j++) {
            atomicAdd(&g_sum[cc * 4 + j],   (double)s[j]);
            atomicAdd(&g_sumsq[cc * 4 + j], (double)q[j]);
        }
    }
}

template<int C>
__global__ void stats_only_kernel(const float* __restrict__ y) {
    const int c4n = C / 4;
    const int ROWS = 256 / c4n;
    int cc = threadIdx.x % c4n;
    int rg = threadIdx.x / c4n;
    float s[4] = {0, 0, 0, 0}, q[4] = {0, 0, 0, 0};
    for (int r = blockIdx.x * ROWS + rg; r < N_NODES; r += gridDim.x * ROWS) {
        float4 v = *((const float4*)(y + (size_t)r * C) + cc);
        s[0] += v.x; q[0] += v.x * v.x;
        s[1] += v.y; q[1] += v.y * v.y;
        s[2] += v.z; q[2] += v.z * v.z;
        s[3] += v.w; q[3] += v.w * v.w;
    }
    __shared__ float shs[256 * 4], shq[256 * 4];
#pragma unroll
    for (int j = 0; j < 4; j++) { shs[threadIdx.x * 4 + j] = s[j]; shq[threadIdx.x * 4 + j] = q[j]; }
    __syncthreads();
    if (rg == 0) {
#pragma unroll 1
        for (int g = 1; g < ROWS; g++) {
            int base = (g * c4n + cc) * 4;
#pragma unroll
            for (int j = 0; j < 4; j++) { s[j] += shs[base + j]; q[j] += shq[base + j]; }
        }
#pragma unroll
        for (int j = 0; j < 4; j++) {
            atomicAdd(&g_sum[cc * 4 + j],   (double)s[j]);
            atomicAdd(&g_sumsq[cc * 4 + j], (double)q[j]);
        }
    }
}

__global__ void stats_c1_kernel(const float* __restrict__ v) {
    float s = 0.f, q = 0.f;
    for (int i = blockIdx.x * 256 + threadIdx.x; i < N_NODES; i += gridDim.x * 256) {
        float x = v[i];
        s += x; q += x * x;
    }
    __shared__ float shs[256], shq[256];
    shs[threadIdx.x] = s; shq[threadIdx.x] = q;
    __syncthreads();
    for (int o = 128; o; o >>= 1) {
        if (threadIdx.x < o) { shs[threadIdx.x] += shs[threadIdx.x + o]; shq[threadIdx.x] += shq[threadIdx.x + o]; }
        __syncthreads();
    }
    if (threadIdx.x == 0) {
        atomicAdd(&g_sum[0],   (double)shs[0]);
        atomicAdd(&g_sumsq[0], (double)shq[0]);
    }
}

__global__ void bn_finalize_kernel(const float* __restrict__ gam, const float* __restrict__ bet,
                                   int C, float* __restrict__ oS, float* __restrict__ oH) {
    int c = threadIdx.x;
    if (c >= C) return;
    double mean = g_sum[c] / (double)N_NODES;
    double var = g_sumsq[c] / (double)N_NODES - mean * mean;
    double sc = (double)gam[c] / sqrt(var + (double)BN_EPS);
    oS[c] = (float)sc;
    oH[c] = bet[c] - (float)(mean * sc);
}

// ---------------- gate network ----------------
__global__ void gate1_kernel(const float* __restrict__ y4, const float* __restrict__ gW1,
                             const float* __restrict__ gb1, float* __restrict__ outz) {
    __shared__ float w[32 * 16];
    __shared__ float bb[16], sc[32], sf[32];
    int tid = threadIdx.x;
    for (int i = tid; i < 512; i += 256) w[i] = gW1[i];
    if (tid < 16) bb[tid] = gb1[tid];
    if (tid < 32) { sc[tid] = g_scale4[tid]; sf[tid] = g_shift4[tid]; }
    __syncthreads();
    int row = blockIdx.x * 256 + tid;
    float h[32];
#pragma unroll
    for (int k4 = 0; k4 < 8; k4++) {
        float4 v = *((const float4*)(y4 + (size_t)row * 32) + k4);
        h[k4 * 4 + 0] = fmaf(v.x, sc[k4 * 4 + 0], sf[k4 * 4 + 0]);
        h[k4 * 4 + 1] = fmaf(v.y, sc[k4 * 4 + 1], sf[k4 * 4 + 1]);
        h[k4 * 4 + 2] = fmaf(v.z, sc[k4 * 4 + 2], sf[k4 * 4 + 2]);
        h[k4 * 4 + 3] = fmaf(v.w, sc[k4 * 4 + 3], sf[k4 * 4 + 3]);
    }
    float acc[16];
#pragma unroll
    for (int j = 0; j < 16; j++) acc[j] = bb[j];
#pragma unroll
    for (int k = 0; k < 32; k++)
#pragma unroll
        for (int j = 0; j < 16; j++) acc[j] = fmaf(h[k], w[k * 16 + j], acc[j]);
#pragma unroll
    for (int j4 = 0; j4 < 4; j4++)
        *((float4*)(outz + (size_t)row * 16) + j4) =
            make_float4(acc[j4 * 4], acc[j4 * 4 + 1], acc[j4 * 4 + 2], acc[j4 * 4 + 3]);
}

__global__ void gate2_kernel(const float* __restrict__ z, const float* __restrict__ gW2,
                             const float* __restrict__ gb2, float* __restrict__ out) {
    __shared__ float w[16], sc[16], sf[16], b0;
    int tid = threadIdx.x;
    if (tid < 16) { w[tid] = gW2[tid]; sc[tid] = g_scaleG1[tid]; sf[tid] = g_shiftG1[tid]; }
    if (tid == 0) b0 = gb2[0];
    __syncthreads();
    int row = blockIdx.x * 256 + tid;
    float acc = b0;
#pragma unroll
    for (int k4 = 0; k4 < 4; k4++) {
        float4 v = *((const float4*)(z + (size_t)row * 16) + k4);
        acc = fmaf(fmaxf(fmaf(v.x, sc[k4 * 4 + 0], sf[k4 * 4 + 0]), 0.f), w[k4 * 4 + 0], acc);
        acc = fmaf(fmaxf(fmaf(v.y, sc[k4 * 4 + 1], sf[k4 * 4 + 1]), 0.f), w[k4 * 4 + 1], acc);
        acc = fmaf(fmaxf(fmaf(v.z, sc[k4 * 4 + 2], sf[k4 * 4 + 2]), 0.f), w[k4 * 4 + 2], acc);
        acc = fmaf(fmaxf(fmaf(v.w, sc[k4 * 4 + 3], sf[k4 * 4 + 3]), 0.f), w[k4 * 4 + 3], acc);
    }
    out[row] = acc;
}

// ---------------- pooling + FC + softmax ----------------
__global__ void pool_fc_kernel(const float* __restrict__ y4, const float* __restrict__ g2,
                               const float* __restrict__ fcW, const float* __restrict__ fcb,
                               float* __restrict__ out) {
    int warp = (blockIdx.x * blockDim.x + threadIdx.x) >> 5;
    int lane = threadIdx.x & 31;
    if (warp >= NGRAPH) return;
    int n0 = warp * ONE_STEP;
    const unsigned FULL = 0xffffffffu;
    float scG = g_scaleG2[0], sfG = g_shiftG2[0];
    float gv = (lane < ONE_STEP) ? fmaxf(fmaf(g2[n0 + lane], scG, sfG), 0.f) : -INFINITY;
    float m = gv;
#pragma unroll
    for (int o = 16; o; o >>= 1) m = fmaxf(m, __shfl_xor_sync(FULL, m, o));
    float ev = (lane < ONE_STEP) ? expf(gv - m) : 0.f;
    float s = ev;
#pragma unroll
    for (int o = 16; o; o >>= 1) s += __shfl_xor_sync(FULL, s, o);
    float inv = 1.0f / s;
    float sc4 = g_scale4[lane], sf4 = g_shift4[lane];
    float pooled = 0.f;
#pragma unroll
    for (int i = 0; i < ONE_STEP; i++) {
        float a = __shfl_sync(FULL, ev, i) * inv;
        float hv = fmaf(y4[(size_t)(n0 + i) * 32 + lane], sc4, sf4);
        pooled = fmaf(a, hv, pooled);
    }
    float logits[10];
#pragma unroll
    for (int j = 0; j < 10; j++) {
        float p = pooled * fcW[lane * 10 + j];
#pragma unroll
        for (int o = 16; o; o >>= 1) p += __shfl_xor_sync(FULL, p, o);
        logits[j] = p + fcb[j];
    }
    if (lane == 0) {
        float mx = logits[0];
#pragma unroll
        for (int j = 1; j < 10; j++) mx = fmaxf(mx, logits[j]);
        float ss = 0.f;
        float e[10];
#pragma unroll
        for (int j = 0; j < 10; j++) { e[j] = expf(logits[j] - mx); ss += e[j]; }
        float invs = 1.0f / ss;
#pragma unroll
        for (int j = 0; j < 10; j++) out[warp * 10 + j] = e[j] * invs;
    }
}

// ---------------- host orchestration ----------------
extern "C" void kernel_launch(void* const* d_in, const int* in_sizes, int n_in,
                              void* d_out, int out_size) {
    const float* x    = (const float*)d_in[0];
    const int*   ei   = (const int*)d_in[1];
    const float* W1   = (const float*)d_in[2];
    const float* b1   = (const float*)d_in[3];
    const float* bn1g = (const float*)d_in[4];
    const float* bn1b = (const float*)d_in[5];
    const float* W2   = (const float*)d_in[6];
    const float* b2   = (const float*)d_in[7];
    const float* bn2g = (const float*)d_in[8];
    const float* bn2b = (const float*)d_in[9];
    const float* W3   = (const float*)d_in[10];
    const float* b3   = (const float*)d_in[11];
    const float* bn3g = (const float*)d_in[12];
    const float* bn3b = (const float*)d_in[13];
    const float* W4   = (const float*)d_in[14];
    const float* b4   = (const float*)d_in[15];
    const float* bn4g = (const float*)d_in[16];
    const float* bn4b = (const float*)d_in[17];
    const float* gW1  = (const float*)d_in[18];
    const float* gb1  = (const float*)d_in[19];
    const float* gbn1g = (const float*)d_in[20];
    const float* gbn1b = (const float*)d_in[21];
    const float* gW2  = (const float*)d_in[22];
    const float* gb2  = (const float*)d_in[23];
    const float* gbn2g = (const float*)d_in[24];
    const float* gbn2b = (const float*)d_in[25];
    const float* fcW  = (const float*)d_in[26];
    const float* fcb  = (const float*)d_in[27];
    float* out = (float*)d_out;

    float *buf0, *buf1, *buf2;
    float *scA, *shA, *sc4, *sh4, *scG1, *shG1, *scG2, *shG2;
    cudaGetSymbolAddress((void**)&buf0, g_buf0);
    cudaGetSymbolAddress((void**)&buf1, g_buf1);
    cudaGetSymbolAddress((void**)&buf2, g_buf2);
    cudaGetSymbolAddress((void**)&scA, g_scaleA);
    cudaGetSymbolAddress((void**)&shA, g_shiftA);
    cudaGetSymbolAddress((void**)&sc4, g_scale4);
    cudaGetSymbolAddress((void**)&sh4, g_shift4);
    cudaGetSymbolAddress((void**)&scG1, g_scaleG1);
    cudaGetSymbolAddress((void**)&shG1, g_shiftG1);
    cudaGetSymbolAddress((void**)&scG2, g_scaleG2);
    cudaGetSymbolAddress((void**)&shG2, g_shiftG2);

    const int GRID = N_NODES / 128;  // 896
    // smem words: Ah+Al = 2*128*36, Bh+Bl = 2*32*(BN+8), affine 2*K floats
    const int SM_L1 = (2 * 128 * 36 + 2 * 32 * 136) * 4;            // 71680
    const int SM_L2 = (2 * 128 * 36 + 2 * 32 * 136) * 4;            // 71680
    const int SM_L3 = (2 * 128 * 36 + 2 * 32 * 72 + 2 * 256) * 4;   // 57344
    cudaFuncSetAttribute((const void*)mma_gemm_kernel<128, 128, 512, false, 0>,
                         cudaFuncAttributeMaxDynamicSharedMemorySize, SM_L1);
    cudaFuncSetAttribute((const void*)mma_gemm_kernel<256, 128, 128, false, 1>,
                         cudaFuncAttributeMaxDynamicSharedMemorySize, SM_L2);
    cudaFuncSetAttribute((const void*)mma_gemm_kernel<64, 64, 256, true, 0>,
                         cudaFuncAttributeMaxDynamicSharedMemorySize, SM_L3);

    // degree / rsqrt normalization
    deg_zero_kernel<<<(N_NODES + 255) / 256, 256>>>();
    deg_count_kernel<<<(N_EDGES + 255) / 256, 256>>>(ei);
    deg_rsqrt_kernel<<<(N_NODES + 255) / 256, 256>>>();

    // ---- Layer 1 (512 -> 128): 3xTF32 mma GEMM, then aggregate ----
    mma_gemm_kernel<128, 128, 512, false, 0><<<dim3(1, GRID), 256, SM_L1>>>(x, W1, nullptr, buf1, buf2);
    edge_agg_kernel<128, false><<<N_EDGES / 8, 256>>>(ei, buf1, buf2);
    zero_stats_kernel<<<1, 256>>>();
    combine_stats_kernel<128><<<512, 256>>>(buf2, b1, buf0);
    bn_finalize_kernel<<<1, 128>>>(bn1g, bn1b, 128, scA, shA);

    // ---- Layer 2 (128 -> 256): aggregate first (BN fused), 3xTF32 GEMM + relu ----
    self_init_affine_kernel<128><<<(N_NODES * 32 + 255) / 256, 256>>>(buf0, buf2);
    edge_agg_kernel<128, true><<<N_EDGES / 8, 256>>>(ei, buf0, buf2);
    mma_gemm_kernel<256, 128, 128, false, 1><<<dim3(2, GRID), 256, SM_L2>>>(buf2, W2, b2, buf0, nullptr);
    zero_stats_kernel<<<1, 256>>>();
    stats_only_kernel<256><<<512, 256>>>(buf0);
    bn_finalize_kernel<<<1, 256>>>(bn2g, bn2b, 256, scA, shA);

    // ---- Layer 3 (256 -> 64): 3xTF32 GEMM (BN fused into A load), aggregate ----
    mma_gemm_kernel<64, 64, 256, true, 0><<<dim3(1, GRID), 256, SM_L3>>>(buf0, W3, nullptr, buf1, buf2);
    edge_agg_kernel<64, false><<<N_EDGES / 16, 256>>>(ei, buf1, buf2);
    zero_stats_kernel<<<1, 256>>>();
    combine_stats_kernel<64><<<512, 256>>>(buf2, b3, buf0);
    bn_finalize_kernel<<<1, 64>>>(bn3g, bn3b, 64, scA, shA);

    // ---- Layer 4 (64 -> 32): fp32 GEMM (cheap), aggregate ----
    gemm_kernel<32, 2, 0, true><<<dim3(1, GRID), 256>>>(buf0, W4, nullptr, buf1, buf2, 64, 32);
    edge_agg_kernel<32, false><<<N_EDGES / 32, 256>>>(ei, buf1, buf2);
    zero_stats_kernel<<<1, 256>>>();
    combine_stats_kernel<32><<<512, 256>>>(buf2, b4, buf0);
    bn_finalize_kernel<<<1, 32>>>(bn4g, bn4b, 32, sc4, sh4);

    // ---- gate layer 1 ----
    gate1_kernel<<<N_NODES / 256, 256>>>(buf0, gW1, gb1, buf1);
    zero_stats_kernel<<<1, 256>>>();
    stats_only_kernel<16><<<512, 256>>>(buf1);
    bn_finalize_kernel<<<1, 16>>>(gbn1g, gbn1b, 16, scG1, shG1);

    // ---- gate layer 2 ----
    gate2_kernel<<<N_NODES / 256, 256>>>(buf1, gW2, gb2, buf2);
    zero_stats_kernel<<<1, 256>>>();
    stats_c1_kernel<<<128, 256>>>(buf2);
    bn_finalize_kernel<<<1, 32>>>(gbn2g, gbn2b, 1, scG2, shG2);

    // ---- segment softmax pooling + FC + softmax ----
    pool_fc_kernel<<<(NGRAPH * 32 + 255) / 256, 256>>>(buf0, buf2, fcW, fcb, out);
}